// round 12
// baseline (speedup 1.0000x reference)
#include <cuda_runtime.h>
#include <cuda_fp16.h>
#include <math.h>

#define NN 100000
#define NE 1000000
#define DIM 64
#define KSTEPS 10
#define FULLMASK 0xffffffffu

// lookback state encoding: bits 30..31 = status (0 invalid, 1 AGG, 2 INC)
#define ST_AGG (1u << 30)
#define ST_INC (2u << 30)
#define ST_VAL(x) ((x) & ((1u << 30) - 1))

// ---------------- static scratch (no allocations allowed) ----------------
__device__ int     g_deg[2 * NN];           // [0..NN) out_deg, [NN..2NN) in_deg
__device__ float2  g_norm[NN];              // (src_norm, dst_norm)
__device__ int     g_row_ptr[NN + 1];
__device__ int     g_cursor[NN];            // running fill cursor (starts at prefix)
__device__ int     g_ecol[NE];              // src ids grouped by dst (CSR)
// state stored as 16B granules: row = 8 x uint4 (64 halves)
__device__ __align__(128) uint4 g_y0[(size_t)NN * 8];
__device__ __align__(128) uint4 g_y1[(size_t)NN * 8];
__device__ __align__(128) uint4 g_fh[(size_t)NN * 8];  // fp16 feat (unscaled)
__device__ __align__(128) uint4 g_z0[(size_t)NN * 8];  // fp16 src_norm*feat
__device__ unsigned g_state[128];           // lookback states

// per-warp dtype probe: int64 edge data has all-zero odd 32-bit words.
// P(int32 misdetect) = P(32 random node ids all zero) ~ 1e-160.
__device__ __forceinline__ int detect64(const int* __restrict__ s) {
    int lane = threadIdx.x & 31;
    int w = s[2 * lane + 1];
    unsigned nz = __ballot_sync(FULLMASK, w != 0);
    return nz == 0u;
}

__device__ __forceinline__ int edge_at(const int* __restrict__ b, int i, int is64) {
    return b[is64 ? (i << 1) : i];
}

__global__ void k_count(const int* __restrict__ src,
                        const int* __restrict__ dst, int e) {
    int i = blockIdx.x * blockDim.x + threadIdx.x;
    int is64 = detect64(src);
    if (i < e) {
        atomicAdd(&g_deg[edge_at(src, i, is64)], 1);
        atomicAdd(&g_deg[NN + edge_at(dst, i, is64)], 1);
    }
}

// Fused: exclusive scan of in_deg (decoupled lookback, 1 launch) + norm pack
// + fp16 feat caches (unscaled fh, src_norm-scaled z0) + cursor init.
__global__ void __launch_bounds__(1024)
k_scan(const float* __restrict__ feat, int n, int etotal, int n8) {
    __shared__ int sh[1024];
    __shared__ int sh_run;
    int tid = threadIdx.x;
    int b = blockIdx.x;
    int gid = b * 1024 + tid;

    int v = (gid < n) ? g_deg[NN + gid] : 0;
    sh[tid] = v;
    __syncthreads();
#pragma unroll
    for (int off = 1; off < 1024; off <<= 1) {
        int t = (tid >= off) ? sh[tid - off] : 0;
        __syncthreads();
        sh[tid] += t;
        __syncthreads();
    }
    int total = sh[1023];

    // publish early so successors' lookback completes fast
    if (tid == 0) {
        unsigned pub = (b == 0) ? (ST_INC | (unsigned)total)
                                : (ST_AGG | (unsigned)total);
        atomicExch(&g_state[b], pub);
        if (b == 0) { sh_run = 0; g_row_ptr[n] = etotal; }
    }

    // bulk work rides along: norms + feat caches
    if (gid < n) {
        g_norm[gid] = make_float2(rsqrtf(fmaxf((float)g_deg[gid], 1.0f)),
                                  rsqrtf(fmaxf((float)v, 1.0f)));
    }
    for (int i = gid; i < n8; i += gridDim.x * 1024) {
        int node = i >> 3;
        float sn = rsqrtf(fmaxf((float)g_deg[node], 1.0f));
        float4 f0 = *(const float4*)(feat + (size_t)i * 8);
        float4 f1 = *(const float4*)(feat + (size_t)i * 8 + 4);
        uint4 oh, oz;
        __half2 h;
        h = __floats2half2_rn(f0.x, f0.y); oh.x = *(unsigned*)&h;
        h = __floats2half2_rn(f0.z, f0.w); oh.y = *(unsigned*)&h;
        h = __floats2half2_rn(f1.x, f1.y); oh.z = *(unsigned*)&h;
        h = __floats2half2_rn(f1.z, f1.w); oh.w = *(unsigned*)&h;
        g_fh[i] = oh;
        h = __floats2half2_rn(sn * f0.x, sn * f0.y); oz.x = *(unsigned*)&h;
        h = __floats2half2_rn(sn * f0.z, sn * f0.w); oz.y = *(unsigned*)&h;
        h = __floats2half2_rn(sn * f1.x, sn * f1.y); oz.z = *(unsigned*)&h;
        h = __floats2half2_rn(sn * f1.z, sn * f1.w); oz.w = *(unsigned*)&h;
        g_z0[i] = oz;
    }

    // warp-parallel lookback (warp 0)
    if (b > 0 && tid < 32) {
        int lane = tid;
        int running = 0;
        int p = b - 1;
        while (true) {
            int idx = p - lane;
            unsigned s;
            if (idx >= 0) {
                do { s = *(volatile unsigned*)&g_state[idx]; } while ((s >> 30) == 0);
            } else {
                s = ST_INC | 0u;   // virtual predecessor
            }
            unsigned inc_mask = __ballot_sync(FULLMASK, (s >> 30) == 2u);
            bool has_inc = (inc_mask != 0u);
            // with no INC in the window, ALL 32 lanes contribute
            int f = has_inc ? (__ffs(inc_mask) - 1) : 31;
            int contrib = (lane <= f) ? (int)ST_VAL(s) : 0;
#pragma unroll
            for (int o = 16; o > 0; o >>= 1)
                contrib += __shfl_xor_sync(FULLMASK, contrib, o);
            running += contrib;
            if (has_inc) break;
            p -= 32;
        }
        if (lane == 0) {
            atomicExch(&g_state[b], ST_INC | (unsigned)(running + total));
            sh_run = running;
        }
    }
    __syncthreads();
    int run = sh_run;
    if (gid < n) {
        int pref = run + sh[tid] - v;   // exclusive prefix
        g_row_ptr[gid] = pref;
        g_cursor[gid]  = pref;          // fill cursor starts at prefix
    }
}

__global__ void k_fill(const int* __restrict__ src,
                       const int* __restrict__ dst, int e) {
    int i = blockIdx.x * blockDim.x + threadIdx.x;
    int is64 = detect64(src);
    if (i < e) {
        int s = edge_at(src, i, is64);
        int d = edge_at(dst, i, is64);
        int pos = atomicAdd(&g_cursor[d], 1);   // absolute slot
        g_ecol[pos] = s;
    }
}

// ---------------- Horner propagation (factored norms) ----------------
// State z[v] = sn[v]*y[v] (fp16). Step:
//   y_new[d] = w_k*f[d] + gs*dn[d]*sum_e z[src];  z_new[d] = sn[d]*y_new[d]
// gs = w_K on the first step (z0 = sn*f), else 1. Last step writes fp32 y.
// QUARTER-WARP (8 lanes) per node; lane owns 16B (8 cols) of the 128B row.
__device__ __forceinline__ void add8(uint4 v, float* a) {
    float2 p;
    p = __half22float2(*(__half2*)&v.x); a[0] += p.x; a[1] += p.y;
    p = __half22float2(*(__half2*)&v.y); a[2] += p.x; a[3] += p.y;
    p = __half22float2(*(__half2*)&v.z); a[4] += p.x; a[5] += p.y;
    p = __half22float2(*(__half2*)&v.w); a[6] += p.x; a[7] += p.y;
}

__device__ __forceinline__ void gather_node(const uint4* __restrict__ yin,
                                            int beg, int end, int g, float* a) {
    int i = beg;
    // 4 independent gather chains per quarter (16 per warp) in flight
    for (; i + 4 <= end; i += 4) {
        int s0 = g_ecol[i],     s1 = g_ecol[i + 1];
        int s2 = g_ecol[i + 2], s3 = g_ecol[i + 3];
        uint4 v0 = yin[(size_t)s0 * 8 + g];
        uint4 v1 = yin[(size_t)s1 * 8 + g];
        uint4 v2 = yin[(size_t)s2 * 8 + g];
        uint4 v3 = yin[(size_t)s3 * 8 + g];
        add8(v0, a); add8(v1, a); add8(v2, a); add8(v3, a);
    }
    for (; i + 2 <= end; i += 2) {
        int s0 = g_ecol[i], s1 = g_ecol[i + 1];
        uint4 v0 = yin[(size_t)s0 * 8 + g];
        uint4 v1 = yin[(size_t)s1 * 8 + g];
        add8(v0, a); add8(v1, a);
    }
    if (i < end) {
        uint4 v = yin[(size_t)g_ecol[i] * 8 + g];
        add8(v, a);
    }
}

// middle steps: fp16 in, fp16 out (9 of 10 launches)
__global__ void __launch_bounds__(512)
k_step_mid(const uint4* __restrict__ yin, uint4* __restrict__ yout,
           const uint4* __restrict__ fh, float wk, float gs, int n) {
    int t = blockIdx.x * blockDim.x + threadIdx.x;
    int node = t >> 3;
    if (node >= n) return;
    int g = t & 7;

    float a[8] = {0.f, 0.f, 0.f, 0.f, 0.f, 0.f, 0.f, 0.f};
    gather_node(yin, g_row_ptr[node], g_row_ptr[node + 1], g, a);

    float2 nm = g_norm[node];
    float sc = gs * nm.y;     // gs * dst_norm
    float sn = nm.x;

    uint4 fv = fh[(size_t)node * 8 + g];
    float2 p;
    uint4 o;
    __half2 h;
    p = __half22float2(*(__half2*)&fv.x);
    h = __floats2half2_rn(sn * fmaf(wk, p.x, sc * a[0]),
                          sn * fmaf(wk, p.y, sc * a[1]));
    o.x = *(unsigned*)&h;
    p = __half22float2(*(__half2*)&fv.y);
    h = __floats2half2_rn(sn * fmaf(wk, p.x, sc * a[2]),
                          sn * fmaf(wk, p.y, sc * a[3]));
    o.y = *(unsigned*)&h;
    p = __half22float2(*(__half2*)&fv.z);
    h = __floats2half2_rn(sn * fmaf(wk, p.x, sc * a[4]),
                          sn * fmaf(wk, p.y, sc * a[5]));
    o.z = *(unsigned*)&h;
    p = __half22float2(*(__half2*)&fv.w);
    h = __floats2half2_rn(sn * fmaf(wk, p.x, sc * a[6]),
                          sn * fmaf(wk, p.y, sc * a[7]));
    o.w = *(unsigned*)&h;
    yout[(size_t)node * 8 + g] = o;
}

// last step: fp16 in, fp32 out (exact fp32 feat term)
__global__ void __launch_bounds__(512)
k_step_last(const uint4* __restrict__ yin, const float* __restrict__ feat,
            float* __restrict__ out, float wk, int n) {
    int t = blockIdx.x * blockDim.x + threadIdx.x;
    int node = t >> 3;
    if (node >= n) return;
    int g = t & 7;

    float a[8] = {0.f, 0.f, 0.f, 0.f, 0.f, 0.f, 0.f, 0.f};
    gather_node(yin, g_row_ptr[node], g_row_ptr[node + 1], g, a);

    float sc = g_norm[node].y;   // dst_norm (gs = 1 here)

    const float* fp = feat + (size_t)node * DIM + g * 8;
    float* op = out + (size_t)node * DIM + g * 8;
    float4 f0 = *(const float4*)fp;
    float4 f1 = *(const float4*)(fp + 4);
    float4 r0, r1;
    r0.x = fmaf(wk, f0.x, sc * a[0]); r0.y = fmaf(wk, f0.y, sc * a[1]);
    r0.z = fmaf(wk, f0.z, sc * a[2]); r0.w = fmaf(wk, f0.w, sc * a[3]);
    r1.x = fmaf(wk, f1.x, sc * a[4]); r1.y = fmaf(wk, f1.y, sc * a[5]);
    r1.z = fmaf(wk, f1.z, sc * a[6]); r1.w = fmaf(wk, f1.w, sc * a[7]);
    *(float4*)op = r0;
    *(float4*)(op + 4) = r1;
}

// ---------------- launch ----------------
extern "C" void kernel_launch(void* const* d_in, const int* in_sizes, int n_in,
                              void* d_out, int out_size) {
    const float* feat  = (const float*)d_in[0];
    const int*   src32 = (const int*)d_in[1];
    const int*   dst32 = (const int*)d_in[2];
    float* out = (float*)d_out;

    int n = in_sizes[0] / DIM;   // 100000
    int e = in_sizes[1];         // 1000000

    void *p0, *p1, *p2, *p3, *pd, *ps;
    cudaGetSymbolAddress(&p0, g_y0);
    cudaGetSymbolAddress(&p1, g_y1);
    cudaGetSymbolAddress(&p2, g_fh);
    cudaGetSymbolAddress(&p3, g_z0);
    cudaGetSymbolAddress(&pd, g_deg);
    cudaGetSymbolAddress(&ps, g_state);
    uint4* y0 = (uint4*)p0;
    uint4* y1 = (uint4*)p1;
    uint4* fh = (uint4*)p2;
    uint4* z0 = (uint4*)p3;

    // log weights: w[j] = log(BETA + 1 + j)/denom, BETA = 2
    double logs[KSTEPS + 1]; double denom = 0.0;
    for (int j = 0; j <= KSTEPS; j++) { logs[j] = log(3.0 + (double)j); denom += logs[j]; }

    int nb_e = (e + 255) / 256;
    int nblk = (n + 1023) / 1024;     // 98
    int n8   = n * 8;

    cudaMemsetAsync(pd, 0, sizeof(int) * 2 * NN);
    cudaMemsetAsync(ps, 0, sizeof(unsigned) * 128);
    k_count<<<nb_e, 256>>>(src32, dst32, e);
    k_scan <<<nblk, 1024>>>(feat, n, e, n8);
    k_fill <<<nb_e, 256>>>(src32, dst32, e);

    int nb_s = (n8 + 511) / 512;      // quarter-warp per node, 512-thread blocks
    const uint4* yin = z0;            // first step gathers sn-scaled feat
    uint4* yout = y0;
    for (int k = KSTEPS - 1; k >= 1; k--) {
        float gs = (k == KSTEPS - 1) ? (float)(logs[KSTEPS] / denom) : 1.0f;
        k_step_mid<<<nb_s, 512>>>(yin, yout, fh,
                                  (float)(logs[k] / denom), gs, n);
        yin = yout;
        yout = (yout == y0) ? y1 : y0;
    }
    k_step_last<<<nb_s, 512>>>(yin, feat, out, (float)(logs[0] / denom), n);
}

// round 13
// speedup vs baseline: 1.0297x; 1.0297x over previous
#include <cuda_runtime.h>
#include <cuda_fp16.h>
#include <math.h>

#define NN 100000
#define NE 1000000
#define DIM 64
#define KSTEPS 10
#define FULLMASK 0xffffffffu

// lookback state encoding: bits 30..31 = status (0 invalid, 1 AGG, 2 INC)
#define ST_AGG (1u << 30)
#define ST_INC (2u << 30)
#define ST_VAL(x) ((x) & ((1u << 30) - 1))

// ---------------- static scratch (no allocations allowed) ----------------
__device__ int     g_deg[2 * NN];           // [0..NN) out_deg, [NN..2NN) in_deg
__device__ float2  g_norm[NN];              // (src_norm, dst_norm)
__device__ int     g_row_ptr[NN + 1];
__device__ int     g_cursor[NN];            // running fill cursor (starts at prefix)
__device__ int     g_ecol[NE];              // src ids grouped by dst (CSR)
// state stored as 16B granules: row = 8 x uint4 (64 halves)
__device__ __align__(128) uint4 g_y0[(size_t)NN * 8];
__device__ __align__(128) uint4 g_y1[(size_t)NN * 8];  // also holds initial sn*feat
__device__ __align__(128) uint4 g_fh[(size_t)NN * 8];  // fp16 feat (unscaled)
__device__ unsigned g_state[128];           // lookback states

// per-warp dtype probe: int64 edge data has all-zero odd 32-bit words.
// P(int32 misdetect) = P(32 random node ids all zero) ~ 1e-160.
__device__ __forceinline__ int detect64(const int* __restrict__ s) {
    int lane = threadIdx.x & 31;
    int w = s[2 * lane + 1];
    unsigned nz = __ballot_sync(FULLMASK, w != 0);
    return nz == 0u;
}

__device__ __forceinline__ int edge_at(const int* __restrict__ b, int i, int is64) {
    return b[is64 ? (i << 1) : i];
}

__global__ void k_count(const int* __restrict__ src,
                        const int* __restrict__ dst, int e) {
    int i = blockIdx.x * blockDim.x + threadIdx.x;
    int is64 = detect64(src);
    if (i < e) {
        atomicAdd(&g_deg[edge_at(src, i, is64)], 1);
        atomicAdd(&g_deg[NN + edge_at(dst, i, is64)], 1);
    }
}

// Fused: exclusive scan of in_deg (decoupled lookback, 1 launch) + norm pack
// + fp16 feat caches (unscaled -> g_fh, src_norm-scaled -> g_y1) + cursor init.
__global__ void __launch_bounds__(1024)
k_scan(const float* __restrict__ feat, int n, int etotal, int n8) {
    __shared__ int sh[1024];
    __shared__ int sh_run;
    int tid = threadIdx.x;
    int b = blockIdx.x;
    int gid = b * 1024 + tid;

    int v = (gid < n) ? g_deg[NN + gid] : 0;
    sh[tid] = v;
    __syncthreads();
#pragma unroll
    for (int off = 1; off < 1024; off <<= 1) {
        int t = (tid >= off) ? sh[tid - off] : 0;
        __syncthreads();
        sh[tid] += t;
        __syncthreads();
    }
    int total = sh[1023];

    // publish early so successors' lookback completes fast
    if (tid == 0) {
        unsigned pub = (b == 0) ? (ST_INC | (unsigned)total)
                                : (ST_AGG | (unsigned)total);
        atomicExch(&g_state[b], pub);
        if (b == 0) { sh_run = 0; g_row_ptr[n] = etotal; }
    }

    // bulk work rides along: norms + feat caches
    if (gid < n) {
        g_norm[gid] = make_float2(rsqrtf(fmaxf((float)g_deg[gid], 1.0f)),
                                  rsqrtf(fmaxf((float)v, 1.0f)));
    }
    for (int i = gid; i < n8; i += gridDim.x * 1024) {
        int node = i >> 3;
        float sn = rsqrtf(fmaxf((float)g_deg[node], 1.0f));
        float4 f0 = *(const float4*)(feat + (size_t)i * 8);
        float4 f1 = *(const float4*)(feat + (size_t)i * 8 + 4);
        uint4 oh, oz;
        __half2 h;
        h = __floats2half2_rn(f0.x, f0.y); oh.x = *(unsigned*)&h;
        h = __floats2half2_rn(f0.z, f0.w); oh.y = *(unsigned*)&h;
        h = __floats2half2_rn(f1.x, f1.y); oh.z = *(unsigned*)&h;
        h = __floats2half2_rn(f1.z, f1.w); oh.w = *(unsigned*)&h;
        g_fh[i] = oh;
        h = __floats2half2_rn(sn * f0.x, sn * f0.y); oz.x = *(unsigned*)&h;
        h = __floats2half2_rn(sn * f0.z, sn * f0.w); oz.y = *(unsigned*)&h;
        h = __floats2half2_rn(sn * f1.x, sn * f1.y); oz.z = *(unsigned*)&h;
        h = __floats2half2_rn(sn * f1.z, sn * f1.w); oz.w = *(unsigned*)&h;
        g_y1[i] = oz;                       // initial state lives in y1
    }

    // warp-parallel lookback (warp 0)
    if (b > 0 && tid < 32) {
        int lane = tid;
        int running = 0;
        int p = b - 1;
        while (true) {
            int idx = p - lane;
            unsigned s;
            if (idx >= 0) {
                do { s = *(volatile unsigned*)&g_state[idx]; } while ((s >> 30) == 0);
            } else {
                s = ST_INC | 0u;   // virtual predecessor
            }
            unsigned inc_mask = __ballot_sync(FULLMASK, (s >> 30) == 2u);
            bool has_inc = (inc_mask != 0u);
            // with no INC in the window, ALL 32 lanes contribute
            int f = has_inc ? (__ffs(inc_mask) - 1) : 31;
            int contrib = (lane <= f) ? (int)ST_VAL(s) : 0;
#pragma unroll
            for (int o = 16; o > 0; o >>= 1)
                contrib += __shfl_xor_sync(FULLMASK, contrib, o);
            running += contrib;
            if (has_inc) break;
            p -= 32;
        }
        if (lane == 0) {
            atomicExch(&g_state[b], ST_INC | (unsigned)(running + total));
            sh_run = running;
        }
    }
    __syncthreads();
    int run = sh_run;
    if (gid < n) {
        int pref = run + sh[tid] - v;   // exclusive prefix
        g_row_ptr[gid] = pref;
        g_cursor[gid]  = pref;          // fill cursor starts at prefix
    }
}

__global__ void k_fill(const int* __restrict__ src,
                       const int* __restrict__ dst, int e) {
    int i = blockIdx.x * blockDim.x + threadIdx.x;
    int is64 = detect64(src);
    if (i < e) {
        int s = edge_at(src, i, is64);
        int d = edge_at(dst, i, is64);
        int pos = atomicAdd(&g_cursor[d], 1);   // absolute slot
        g_ecol[pos] = s;
    }
}

// ---------------- Horner propagation (factored norms) ----------------
// State z[v] = sn[v]*y[v] (fp16). Step:
//   y_new[d] = w_k*f[d] + gs*dn[d]*sum_e z[src];  z_new[d] = sn[d]*y_new[d]
// gs = w_K on the first step (y1 = sn*f), else 1. Last step writes fp32 y.
// QUARTER-WARP (8 lanes) per node; lane owns 16B (8 cols) of the 128B row.
__device__ __forceinline__ void add8(uint4 v, float* a) {
    float2 p;
    p = __half22float2(*(__half2*)&v.x); a[0] += p.x; a[1] += p.y;
    p = __half22float2(*(__half2*)&v.y); a[2] += p.x; a[3] += p.y;
    p = __half22float2(*(__half2*)&v.z); a[4] += p.x; a[5] += p.y;
    p = __half22float2(*(__half2*)&v.w); a[6] += p.x; a[7] += p.y;
}

__device__ __forceinline__ void gather_node(const uint4* __restrict__ yin,
                                            int beg, int end, int g, float* a) {
    int i = beg;
    // 4 independent gather chains per quarter (16 per warp) in flight
    for (; i + 4 <= end; i += 4) {
        int s0 = g_ecol[i],     s1 = g_ecol[i + 1];
        int s2 = g_ecol[i + 2], s3 = g_ecol[i + 3];
        uint4 v0 = yin[(size_t)s0 * 8 + g];
        uint4 v1 = yin[(size_t)s1 * 8 + g];
        uint4 v2 = yin[(size_t)s2 * 8 + g];
        uint4 v3 = yin[(size_t)s3 * 8 + g];
        add8(v0, a); add8(v1, a); add8(v2, a); add8(v3, a);
    }
    for (; i + 2 <= end; i += 2) {
        int s0 = g_ecol[i], s1 = g_ecol[i + 1];
        uint4 v0 = yin[(size_t)s0 * 8 + g];
        uint4 v1 = yin[(size_t)s1 * 8 + g];
        add8(v0, a); add8(v1, a);
    }
    if (i < end) {
        uint4 v = yin[(size_t)g_ecol[i] * 8 + g];
        add8(v, a);
    }
}

// middle steps: fp16 in, fp16 out (9 of 10 launches)
__global__ void __launch_bounds__(256)
k_step_mid(const uint4* __restrict__ yin, uint4* __restrict__ yout,
           const uint4* __restrict__ fh, float wk, float gs, int n) {
    int t = blockIdx.x * blockDim.x + threadIdx.x;
    int node = t >> 3;
    if (node >= n) return;
    int g = t & 7;

    float a[8] = {0.f, 0.f, 0.f, 0.f, 0.f, 0.f, 0.f, 0.f};
    gather_node(yin, g_row_ptr[node], g_row_ptr[node + 1], g, a);

    float2 nm = g_norm[node];
    float sc = gs * nm.y;     // gs * dst_norm
    float sn = nm.x;

    uint4 fv = fh[(size_t)node * 8 + g];
    float2 p;
    uint4 o;
    __half2 h;
    p = __half22float2(*(__half2*)&fv.x);
    h = __floats2half2_rn(sn * fmaf(wk, p.x, sc * a[0]),
                          sn * fmaf(wk, p.y, sc * a[1]));
    o.x = *(unsigned*)&h;
    p = __half22float2(*(__half2*)&fv.y);
    h = __floats2half2_rn(sn * fmaf(wk, p.x, sc * a[2]),
                          sn * fmaf(wk, p.y, sc * a[3]));
    o.y = *(unsigned*)&h;
    p = __half22float2(*(__half2*)&fv.z);
    h = __floats2half2_rn(sn * fmaf(wk, p.x, sc * a[4]),
                          sn * fmaf(wk, p.y, sc * a[5]));
    o.z = *(unsigned*)&h;
    p = __half22float2(*(__half2*)&fv.w);
    h = __floats2half2_rn(sn * fmaf(wk, p.x, sc * a[6]),
                          sn * fmaf(wk, p.y, sc * a[7]));
    o.w = *(unsigned*)&h;
    yout[(size_t)node * 8 + g] = o;
}

// last step: fp16 in, fp32 out (exact fp32 feat term)
__global__ void __launch_bounds__(256)
k_step_last(const uint4* __restrict__ yin, const float* __restrict__ feat,
            float* __restrict__ out, float wk, int n) {
    int t = blockIdx.x * blockDim.x + threadIdx.x;
    int node = t >> 3;
    if (node >= n) return;
    int g = t & 7;

    float a[8] = {0.f, 0.f, 0.f, 0.f, 0.f, 0.f, 0.f, 0.f};
    gather_node(yin, g_row_ptr[node], g_row_ptr[node + 1], g, a);

    float sc = g_norm[node].y;   // dst_norm (gs = 1 here)

    const float* fp = feat + (size_t)node * DIM + g * 8;
    float* op = out + (size_t)node * DIM + g * 8;
    float4 f0 = *(const float4*)fp;
    float4 f1 = *(const float4*)(fp + 4);
    float4 r0, r1;
    r0.x = fmaf(wk, f0.x, sc * a[0]); r0.y = fmaf(wk, f0.y, sc * a[1]);
    r0.z = fmaf(wk, f0.z, sc * a[2]); r0.w = fmaf(wk, f0.w, sc * a[3]);
    r1.x = fmaf(wk, f1.x, sc * a[4]); r1.y = fmaf(wk, f1.y, sc * a[5]);
    r1.z = fmaf(wk, f1.z, sc * a[6]); r1.w = fmaf(wk, f1.w, sc * a[7]);
    *(float4*)op = r0;
    *(float4*)(op + 4) = r1;
}

// ---------------- launch ----------------
extern "C" void kernel_launch(void* const* d_in, const int* in_sizes, int n_in,
                              void* d_out, int out_size) {
    const float* feat  = (const float*)d_in[0];
    const int*   src32 = (const int*)d_in[1];
    const int*   dst32 = (const int*)d_in[2];
    float* out = (float*)d_out;

    int n = in_sizes[0] / DIM;   // 100000
    int e = in_sizes[1];         // 1000000

    void *p0, *p1, *p2, *pd, *ps;
    cudaGetSymbolAddress(&p0, g_y0);
    cudaGetSymbolAddress(&p1, g_y1);
    cudaGetSymbolAddress(&p2, g_fh);
    cudaGetSymbolAddress(&pd, g_deg);
    cudaGetSymbolAddress(&ps, g_state);
    uint4* y0 = (uint4*)p0;
    uint4* y1 = (uint4*)p1;
    uint4* fh = (uint4*)p2;

    // log weights: w[j] = log(BETA + 1 + j)/denom, BETA = 2
    double logs[KSTEPS + 1]; double denom = 0.0;
    for (int j = 0; j <= KSTEPS; j++) { logs[j] = log(3.0 + (double)j); denom += logs[j]; }

    int nb_e = (e + 255) / 256;
    int nblk = (n + 1023) / 1024;     // 98
    int n8   = n * 8;

    cudaMemsetAsync(pd, 0, sizeof(int) * 2 * NN);
    cudaMemsetAsync(ps, 0, sizeof(unsigned) * 128);
    k_count<<<nb_e, 256>>>(src32, dst32, e);
    k_scan <<<nblk, 1024>>>(feat, n, e, n8);
    k_fill <<<nb_e, 256>>>(src32, dst32, e);

    int nb_s = (n8 + 255) / 256;      // quarter-warp per node, 256-thread blocks
    const uint4* yin = y1;            // initial sn-scaled feat lives in y1
    uint4* yout = y0;
    for (int k = KSTEPS - 1; k >= 1; k--) {
        float gs = (k == KSTEPS - 1) ? (float)(logs[KSTEPS] / denom) : 1.0f;
        k_step_mid<<<nb_s, 256>>>(yin, yout, fh,
                                  (float)(logs[k] / denom), gs, n);
        // swap ping-pong
        uint4* tmp = (uint4*)yin;
        yin = yout;
        yout = (tmp == y0) ? y0 : y1;
        if (yout == yin) yout = (yin == y0) ? y1 : y0;   // safety (no-op)
    }
    k_step_last<<<nb_s, 256>>>(yin, feat, out, (float)(logs[0] / denom), n);
}

// round 14
// speedup vs baseline: 1.0499x; 1.0196x over previous
#include <cuda_runtime.h>
#include <cuda_fp16.h>
#include <math.h>

#define NN 100000
#define NE 1000000
#define DIM 64
#define KSTEPS 10
#define FULLMASK 0xffffffffu

// lookback state encoding: bits 30..31 = status (0 invalid, 1 AGG, 2 INC)
#define ST_AGG (1u << 30)
#define ST_INC (2u << 30)
#define ST_VAL(x) ((x) & ((1u << 30) - 1))

// ---------------- static scratch (no allocations allowed) ----------------
__device__ int     g_out_deg[NN];
__device__ int     g_in_deg[NN];
__device__ float2  g_norm[NN];              // (src_norm, dst_norm)
__device__ int     g_row_ptr[NN + 1];
__device__ int     g_cursor[NN];            // running fill cursor (starts at prefix)
__device__ int     g_ecol[NE];              // src ids grouped by dst (CSR)
// state stored as 16B granules: row = 8 x uint4 (64 halves)
__device__ __align__(128) uint4 g_y0[(size_t)NN * 8];
__device__ __align__(128) uint4 g_y1[(size_t)NN * 8];  // also holds initial sn*feat
__device__ __align__(128) uint4 g_fh[(size_t)NN * 8];  // fp16 feat (unscaled)
__device__ volatile unsigned g_state[128];  // lookback states
__device__ int     g_is64;

__device__ __forceinline__ int edge_at(const int* __restrict__ b, int i, int is64) {
    return b[is64 ? (i << 1) : i];
}

// ---------------- init: zero counters + dtype detect ----------------
__global__ void k_init0(const int* __restrict__ src32, int n) {
    int i = blockIdx.x * blockDim.x + threadIdx.x;
    if (i < n) { g_out_deg[i] = 0; g_in_deg[i] = 0; }
    if (i < 128) g_state[i] = 0;
    if (i == 0) g_is64 = 1;
    if (blockIdx.x == 0) {   // int64 data has all-zero odd 32-bit words
        for (int j = threadIdx.x; j < 1024; j += blockDim.x)
            if (src32[2 * j + 1] != 0) g_is64 = 0;
    }
}

__global__ void k_count(const int* __restrict__ src,
                        const int* __restrict__ dst, int e) {
    int i = blockIdx.x * blockDim.x + threadIdx.x;
    int is64 = g_is64;
    if (i < e) {
        atomicAdd(&g_out_deg[edge_at(src, i, is64)], 1);
        atomicAdd(&g_in_deg[edge_at(dst, i, is64)], 1);
    }
}

// Fused: exclusive scan of in_deg (decoupled lookback, 1 launch) + norm pack
// + fp16 feat caches (unscaled -> g_fh, src_norm-scaled -> g_y1) + cursor init.
__global__ void __launch_bounds__(1024)
k_scan(const float* __restrict__ feat, int n, int etotal, int n8) {
    __shared__ int sh[1024];
    __shared__ int sh_run;
    int tid = threadIdx.x;
    int b = blockIdx.x;
    int gid = b * 1024 + tid;

    int v = (gid < n) ? g_in_deg[gid] : 0;
    sh[tid] = v;
    __syncthreads();
#pragma unroll
    for (int off = 1; off < 1024; off <<= 1) {
        int t = (tid >= off) ? sh[tid - off] : 0;
        __syncthreads();
        sh[tid] += t;
        __syncthreads();
    }
    int total = sh[1023];

    // publish early so successors' lookback completes fast
    if (tid == 0) {
        unsigned pub = (b == 0) ? (ST_INC | (unsigned)total)
                                : (ST_AGG | (unsigned)total);
        atomicExch((unsigned*)&g_state[b], pub);
        if (b == 0) { sh_run = 0; g_row_ptr[n] = etotal; }
    }

    // bulk work rides along: norms + feat caches
    if (gid < n) {
        g_norm[gid] = make_float2(rsqrtf(fmaxf((float)g_out_deg[gid], 1.0f)),
                                  rsqrtf(fmaxf((float)v, 1.0f)));
    }
    for (int i = gid; i < n8; i += gridDim.x * 1024) {
        int node = i >> 3;
        float sn = rsqrtf(fmaxf((float)g_out_deg[node], 1.0f));
        float4 f0 = *(const float4*)(feat + (size_t)i * 8);
        float4 f1 = *(const float4*)(feat + (size_t)i * 8 + 4);
        uint4 oh, oz;
        __half2 h;
        h = __floats2half2_rn(f0.x, f0.y); oh.x = *(unsigned*)&h;
        h = __floats2half2_rn(f0.z, f0.w); oh.y = *(unsigned*)&h;
        h = __floats2half2_rn(f1.x, f1.y); oh.z = *(unsigned*)&h;
        h = __floats2half2_rn(f1.z, f1.w); oh.w = *(unsigned*)&h;
        g_fh[i] = oh;
        h = __floats2half2_rn(sn * f0.x, sn * f0.y); oz.x = *(unsigned*)&h;
        h = __floats2half2_rn(sn * f0.z, sn * f0.w); oz.y = *(unsigned*)&h;
        h = __floats2half2_rn(sn * f1.x, sn * f1.y); oz.z = *(unsigned*)&h;
        h = __floats2half2_rn(sn * f1.z, sn * f1.w); oz.w = *(unsigned*)&h;
        g_y1[i] = oz;                       // initial state lives in y1 (no z0 buffer)
    }

    // warp-parallel lookback (warp 0)
    if (b > 0 && tid < 32) {
        int lane = tid;
        int running = 0;
        int p = b - 1;
        while (true) {
            int idx = p - lane;
            unsigned s;
            if (idx >= 0) {
                do { s = g_state[idx]; } while ((s >> 30) == 0);
            } else {
                s = ST_INC | 0u;   // virtual predecessor
            }
            unsigned inc_mask = __ballot_sync(FULLMASK, (s >> 30) == 2u);
            bool has_inc = (inc_mask != 0u);
            // with no INC in the window, ALL 32 lanes contribute
            int f = has_inc ? (__ffs(inc_mask) - 1) : 31;
            int contrib = (lane <= f) ? (int)ST_VAL(s) : 0;
#pragma unroll
            for (int o = 16; o > 0; o >>= 1)
                contrib += __shfl_xor_sync(FULLMASK, contrib, o);
            running += contrib;
            if (has_inc) break;
            p -= 32;
        }
        if (lane == 0) {
            atomicExch((unsigned*)&g_state[b], ST_INC | (unsigned)(running + total));
            sh_run = running;
        }
    }
    __syncthreads();
    int run = sh_run;
    if (gid < n) {
        int pref = run + sh[tid] - v;   // exclusive prefix
        g_row_ptr[gid] = pref;
        g_cursor[gid]  = pref;          // fill cursor starts at prefix
    }
}

__global__ void k_fill(const int* __restrict__ src,
                       const int* __restrict__ dst, int e) {
    int i = blockIdx.x * blockDim.x + threadIdx.x;
    int is64 = g_is64;
    if (i < e) {
        int s = edge_at(src, i, is64);
        int d = edge_at(dst, i, is64);
        int pos = atomicAdd(&g_cursor[d], 1);   // absolute slot
        g_ecol[pos] = s;
    }
}

// ---------------- Horner propagation (factored norms) ----------------
// State z[v] = sn[v]*y[v] (fp16). Step:
//   y_new[d] = w_k*f[d] + gs*dn[d]*sum_e z[src];  z_new[d] = sn[d]*y_new[d]
// gs = w_K on the first step (y1 = sn*f), else 1. Last step writes fp32 y.
// QUARTER-WARP (8 lanes) per node; lane owns 16B (8 cols) of the 128B row.
__device__ __forceinline__ void add8(uint4 v, float* a) {
    float2 p;
    p = __half22float2(*(__half2*)&v.x); a[0] += p.x; a[1] += p.y;
    p = __half22float2(*(__half2*)&v.y); a[2] += p.x; a[3] += p.y;
    p = __half22float2(*(__half2*)&v.z); a[4] += p.x; a[5] += p.y;
    p = __half22float2(*(__half2*)&v.w); a[6] += p.x; a[7] += p.y;
}

__global__ void __launch_bounds__(256)
k_step(const uint4* __restrict__ yin, uint4* __restrict__ yout,
       const uint4* __restrict__ fh, const float* __restrict__ feat,
       float* __restrict__ out, float wk, float gs, int n, int last) {
    int t = blockIdx.x * blockDim.x + threadIdx.x;
    int node = t >> 3;        // quarter-warp per node
    if (node >= n) return;
    int g = t & 7;            // granule: cols g*8 .. g*8+7

    int beg = g_row_ptr[node];
    int end = g_row_ptr[node + 1];

    float a[8] = {0.f, 0.f, 0.f, 0.f, 0.f, 0.f, 0.f, 0.f};
    int i = beg;
    // 4 independent gather chains per quarter (16 per warp) in flight
    for (; i + 4 <= end; i += 4) {
        int s0 = g_ecol[i],     s1 = g_ecol[i + 1];
        int s2 = g_ecol[i + 2], s3 = g_ecol[i + 3];
        uint4 v0 = yin[(size_t)s0 * 8 + g];
        uint4 v1 = yin[(size_t)s1 * 8 + g];
        uint4 v2 = yin[(size_t)s2 * 8 + g];
        uint4 v3 = yin[(size_t)s3 * 8 + g];
        add8(v0, a); add8(v1, a); add8(v2, a); add8(v3, a);
    }
    for (; i + 2 <= end; i += 2) {
        int s0 = g_ecol[i], s1 = g_ecol[i + 1];
        uint4 v0 = yin[(size_t)s0 * 8 + g];
        uint4 v1 = yin[(size_t)s1 * 8 + g];
        add8(v0, a); add8(v1, a);
    }
    if (i < end) {
        uint4 v = yin[(size_t)g_ecol[i] * 8 + g];
        add8(v, a);
    }

    float2 nm = g_norm[node];
    float sc = gs * nm.y;     // gs * dst_norm

    if (last) {
        const float* fp = feat + (size_t)node * DIM + g * 8;
        float* op = out + (size_t)node * DIM + g * 8;
        float4 f0 = *(const float4*)fp;
        float4 f1 = *(const float4*)(fp + 4);
        float4 r0, r1;
        r0.x = fmaf(wk, f0.x, sc * a[0]); r0.y = fmaf(wk, f0.y, sc * a[1]);
        r0.z = fmaf(wk, f0.z, sc * a[2]); r0.w = fmaf(wk, f0.w, sc * a[3]);
        r1.x = fmaf(wk, f1.x, sc * a[4]); r1.y = fmaf(wk, f1.y, sc * a[5]);
        r1.z = fmaf(wk, f1.z, sc * a[6]); r1.w = fmaf(wk, f1.w, sc * a[7]);
        *(float4*)op = r0;
        *(float4*)(op + 4) = r1;
    } else {
        uint4 fv = fh[(size_t)node * 8 + g];
        float sn = nm.x;
        float2 p;
        uint4 o;
        __half2 h;
        p = __half22float2(*(__half2*)&fv.x);
        h = __floats2half2_rn(sn * fmaf(wk, p.x, sc * a[0]),
                              sn * fmaf(wk, p.y, sc * a[1]));
        o.x = *(unsigned*)&h;
        p = __half22float2(*(__half2*)&fv.y);
        h = __floats2half2_rn(sn * fmaf(wk, p.x, sc * a[2]),
                              sn * fmaf(wk, p.y, sc * a[3]));
        o.y = *(unsigned*)&h;
        p = __half22float2(*(__half2*)&fv.z);
        h = __floats2half2_rn(sn * fmaf(wk, p.x, sc * a[4]),
                              sn * fmaf(wk, p.y, sc * a[5]));
        o.z = *(unsigned*)&h;
        p = __half22float2(*(__half2*)&fv.w);
        h = __floats2half2_rn(sn * fmaf(wk, p.x, sc * a[6]),
                              sn * fmaf(wk, p.y, sc * a[7]));
        o.w = *(unsigned*)&h;
        yout[(size_t)node * 8 + g] = o;
    }
}

// ---------------- launch ----------------
extern "C" void kernel_launch(void* const* d_in, const int* in_sizes, int n_in,
                              void* d_out, int out_size) {
    const float* feat  = (const float*)d_in[0];
    const int*   src32 = (const int*)d_in[1];
    const int*   dst32 = (const int*)d_in[2];
    float* out = (float*)d_out;

    int n = in_sizes[0] / DIM;   // 100000
    int e = in_sizes[1];         // 1000000

    void *p0, *p1, *p2;
    cudaGetSymbolAddress(&p0, g_y0);
    cudaGetSymbolAddress(&p1, g_y1);
    cudaGetSymbolAddress(&p2, g_fh);
    uint4* y0 = (uint4*)p0;
    uint4* y1 = (uint4*)p1;
    uint4* fh = (uint4*)p2;

    // log weights: w[j] = log(BETA + 1 + j)/denom, BETA = 2
    double logs[KSTEPS + 1]; double denom = 0.0;
    for (int j = 0; j <= KSTEPS; j++) { logs[j] = log(3.0 + (double)j); denom += logs[j]; }

    int nb_n = (n + 255) / 256;
    int nb_e = (e + 255) / 256;
    int nblk = (n + 1023) / 1024;     // 98
    int n8   = n * 8;

    k_init0<<<nb_n, 256>>>(src32, n);
    k_count<<<nb_e, 256>>>(src32, dst32, e);
    k_scan <<<nblk, 1024>>>(feat, n, e, n8);
    k_fill <<<nb_e, 256>>>(src32, dst32, e);

    int nb_s = (n8 + 255) / 256;      // quarter-warp per node
    const uint4* yin = y1;            // initial sn-scaled feat lives in y1
    uint4* yout = y0;
    for (int k = KSTEPS - 1; k >= 0; k--) {
        float gs = (k == KSTEPS - 1) ? (float)(logs[KSTEPS] / denom) : 1.0f;
        k_step<<<nb_s, 256>>>(yin, yout, fh, feat, out,
                              (float)(logs[k] / denom), gs, n, k == 0);
        const uint4* tmp = yin;
        yin = yout;
        yout = (uint4*)tmp;
    }
}